// round 8
// baseline (speedup 1.0000x reference)
#include <cuda_runtime.h>
#include <cuda_fp16.h>
#include <cuda_bf16.h>

#define NMAX 100000
#define EMAX 1600000
#define D 64
#define SCAN_B 1024
#define SCAN_MAXBLK 128

// __device__ scratch (no allocations allowed)
__device__ int    g_deg[NMAX];
__device__ int    g_rowstart[NMAX];
__device__ int    g_cursor[NMAX];
__device__ float  g_dinv[NMAX];
__device__ __half g_xh[(size_t)NMAX * D];   // fp16, pre-scaled by dinv[node]
__device__ int    g_ecol[EMAX];

// decoupled-lookback state: ONE 64-bit word per block = (flag<<32) | value.
// flag: 0 = invalid, 1 = aggregate, 2 = inclusive prefix. 8B loads/stores are
// single-copy atomic, so readers get a consistent (flag, value) snapshot.
__device__ volatile unsigned long long g_scan_pair[SCAN_MAXBLK];

// packed fp32x2 FMA (Blackwell)
__device__ __forceinline__ void fma_f32x2(unsigned long long& d,
                                          unsigned long long a,
                                          unsigned long long b,
                                          unsigned long long c) {
    asm("fma.rn.f32x2 %0, %1, %2, %3;" : "=l"(d) : "l"(a), "l"(b), "l"(c));
}
__device__ __forceinline__ unsigned smem_u32(const void* p) {
    return (unsigned)__cvta_generic_to_shared(p);
}
__device__ __forceinline__ void cp_async16(unsigned s, const void* g) {
    asm volatile("cp.async.cg.shared.global [%0], [%1], 16;" :: "r"(s), "l"(g));
}
__device__ __forceinline__ void cp_commit() { asm volatile("cp.async.commit_group;"); }
template <int N> __device__ __forceinline__ void cp_wait() {
    asm volatile("cp.async.wait_group %0;" :: "n"(N));
}

// ---------------------------------------------------------------------------
// zero degree + scan state
// ---------------------------------------------------------------------------
__global__ void k_zero(int N) {
    int i = blockIdx.x * blockDim.x + threadIdx.x;
    if (i < N) g_deg[i] = 0;
    if (i < SCAN_MAXBLK) g_scan_pair[i] = 0ULL;
}

// ---------------------------------------------------------------------------
// degree histogram
// ---------------------------------------------------------------------------
__global__ void k_degree(const int* __restrict__ rowp, int E) {
    int i = blockIdx.x * blockDim.x + threadIdx.x;
    int stride = gridDim.x * blockDim.x;
    for (int e = i; e < E; e += stride) atomicAdd(&g_deg[__ldg(rowp + e)], 1);
}

// ---------------------------------------------------------------------------
// single-pass scan (decoupled lookback, packed flag|value): g_deg ->
// exclusive g_rowstart, cursors, and dinv. 98 blocks co-resident on 148 SMs.
// ---------------------------------------------------------------------------
__global__ void __launch_bounds__(SCAN_B) k_scan(int N) {
    __shared__ int wsum[32];
    __shared__ int s_base;

    int bid = blockIdx.x;
    int i = bid * SCAN_B + threadIdx.x;
    int lane = threadIdx.x & 31;
    int wid = threadIdx.x >> 5;

    int v = (i < N) ? g_deg[i] : 0;

    // warp inclusive scan
    int s = v;
#pragma unroll
    for (int off = 1; off < 32; off <<= 1) {
        int t = __shfl_up_sync(0xffffffffu, s, off);
        if (lane >= off) s += t;
    }
    if (lane == 31) wsum[wid] = s;
    __syncthreads();
    if (wid == 0) {
        int ws = wsum[lane];
#pragma unroll
        for (int off = 1; off < 32; off <<= 1) {
            int t = __shfl_up_sync(0xffffffffu, ws, off);
            if (lane >= off) ws += t;
        }
        wsum[lane] = ws;
    }
    __syncthreads();
    int incl = s + ((wid > 0) ? wsum[wid - 1] : 0);   // block-local inclusive
    int block_total = wsum[31];

    // publish + lookback (thread 0); flag and value travel in one 8B word
    if (threadIdx.x == 0) {
        if (bid == 0) {
            g_scan_pair[0] = (2ULL << 32) | (unsigned)block_total;
            s_base = 0;
        } else {
            g_scan_pair[bid] = (1ULL << 32) | (unsigned)block_total;
            int base = 0;
            int j = bid - 1;
            while (true) {
                unsigned long long p;
                do { p = g_scan_pair[j]; } while ((p >> 32) == 0ULL);
                base += (int)(unsigned)p;
                if ((p >> 32) == 2ULL) break;
                j--;
            }
            g_scan_pair[bid] = (2ULL << 32) | (unsigned)(base + block_total);
            s_base = base;
        }
    }
    __syncthreads();

    if (i < N) {
        int excl = s_base + incl - v;
        g_rowstart[i] = excl;
        g_cursor[i] = excl;
        g_dinv[i] = (v > 0) ? rsqrtf((float)v) : 0.0f;
    }
}

// ---------------------------------------------------------------------------
// CSR fill: atomic ticket per row, store column index
// ---------------------------------------------------------------------------
__global__ void k_fill(const int* __restrict__ ei, int E) {
    int i = blockIdx.x * blockDim.x + threadIdx.x;
    int stride = gridDim.x * blockDim.x;
    const int* rowp = ei;
    const int* colp = ei + E;
    for (int e = i; e < E; e += stride) {
        int r = __ldg(rowp + e);
        int c = __ldg(colp + e);
        int p = atomicAdd(&g_cursor[r], 1);
        g_ecol[p] = c;
    }
}

// ---------------------------------------------------------------------------
// GEMM: xh_h[r] = fp16( dinv[r] * (x[r] @ W^T) ).  Persistent, W-stationary
// (f32x2), cp.async double-buffered tiles, 32 rows/tile, 8 rows/thread.
// ---------------------------------------------------------------------------
#define GEMM_ROWS 32
#define RPT 8
#define GEMM_GRID 296

__global__ void __launch_bounds__(256) k_gemm(const float* __restrict__ x,
                                              const float* __restrict__ W, int N) {
    __shared__ float  Ws[D * (D + 1)];
    __shared__ float2 xs[2][GEMM_ROWS][D / 2];

    int tid = threadIdx.x;
    int tx = tid & 63;
    int ty = tid >> 6;

    for (int i = tid; i < D * D; i += 256)
        Ws[(i >> 6) * (D + 1) + (i & 63)] = W[i];
    __syncthreads();

    unsigned long long w2[D / 2];
#pragma unroll
    for (int k2 = 0; k2 < D / 2; k2++) {
        float2 p = make_float2(Ws[tx * (D + 1) + 2 * k2], Ws[tx * (D + 1) + 2 * k2 + 1]);
        w2[k2] = *reinterpret_cast<unsigned long long*>(&p);
    }
    __syncthreads();

    int ntiles = (N + GEMM_ROWS - 1) / GEMM_ROWS;

    auto issue = [&](int t, int buf) {
        const float4* src = reinterpret_cast<const float4*>(x + (size_t)t * GEMM_ROWS * D);
        int limit = (N - t * GEMM_ROWS) * (D / 4);
        unsigned sbase = smem_u32(&xs[buf][0][0]);
#pragma unroll
        for (int rnd = 0; rnd < 2; rnd++) {
            int v = tid + rnd * 256;
            if (v < 512 && v < limit) cp_async16(sbase + v * 16, src + v);
        }
        cp_commit();
    };

    int t = blockIdx.x;
    if (t < ntiles) issue(t, 0);
    int buf = 0;

    for (; t < ntiles; t += GEMM_GRID) {
        int tn = t + GEMM_GRID;
        bool have_next = (tn < ntiles);
        if (have_next) issue(tn, buf ^ 1);

        if (have_next) cp_wait<1>(); else cp_wait<0>();
        __syncthreads();

        int r0 = ty * RPT;
        unsigned long long acc[RPT];
#pragma unroll
        for (int i = 0; i < RPT; i++) acc[i] = 0ULL;

#pragma unroll
        for (int k2 = 0; k2 < D / 2; k2++) {
            unsigned long long wreg = w2[k2];
#pragma unroll
            for (int i = 0; i < RPT; i++) {
                float2 xv = xs[buf][r0 + i][k2];
                unsigned long long xp = *reinterpret_cast<unsigned long long*>(&xv);
                fma_f32x2(acc[i], xp, wreg, acc[i]);
            }
        }

        int rb = t * GEMM_ROWS;
#pragma unroll
        for (int i = 0; i < RPT; i++) {
            int r = rb + r0 + i;
            if (r < N) {
                float2 p = *reinterpret_cast<float2*>(&acc[i]);
                float dr = g_dinv[r];
                g_xh[(size_t)r * D + tx] = __float2half_rn(dr * (p.x + p.y));
            }
        }
        __syncthreads();
        buf ^= 1;
    }
}

// ---------------------------------------------------------------------------
// Gather: warp per row, fp16 pre-scaled rows, pure half2->float2 accumulate.
// out[r] = dinv[r] * sum_j xh_h[c_j]
// ---------------------------------------------------------------------------
__global__ void k_gather(float* __restrict__ out, int N) {
    int gtid = blockIdx.x * blockDim.x + threadIdx.x;
    int warp = gtid >> 5;
    int lane = threadIdx.x & 31;
    int nwarps = (gridDim.x * blockDim.x) >> 5;

    const __half2* xh2 = reinterpret_cast<const __half2*>(g_xh);

    for (int r = warp; r < N; r += nwarps) {
        int s = g_rowstart[r];
        int e = s + g_deg[r];

        float ax = 0.f, ay = 0.f, bx = 0.f, by = 0.f;
        float cx = 0.f, cy = 0.f, dx = 0.f, dy = 0.f;

        int j = s;
        for (; j + 3 < e; j += 4) {
            int c0 = g_ecol[j];
            int c1 = g_ecol[j + 1];
            int c2 = g_ecol[j + 2];
            int c3 = g_ecol[j + 3];
            float2 f0 = __half22float2(xh2[(size_t)c0 * 32 + lane]);
            float2 f1 = __half22float2(xh2[(size_t)c1 * 32 + lane]);
            float2 f2 = __half22float2(xh2[(size_t)c2 * 32 + lane]);
            float2 f3 = __half22float2(xh2[(size_t)c3 * 32 + lane]);
            ax += f0.x; ay += f0.y;
            bx += f1.x; by += f1.y;
            cx += f2.x; cy += f2.y;
            dx += f3.x; dy += f3.y;
        }
        for (; j < e; j++) {
            int c = g_ecol[j];
            float2 f = __half22float2(xh2[(size_t)c * 32 + lane]);
            ax += f.x; ay += f.y;
        }

        float dr = g_dinv[r];
        float2 res = make_float2(dr * (ax + bx + cx + dx),
                                 dr * (ay + by + cy + dy));
        reinterpret_cast<float2*>(out)[(size_t)r * 32 + lane] = res;
    }
}

// ---------------------------------------------------------------------------
// launch
// ---------------------------------------------------------------------------
extern "C" void kernel_launch(void* const* d_in, const int* in_sizes, int n_in,
                              void* d_out, int out_size) {
    const int*   edge_index = (const int*)d_in[0];
    const float* x          = (const float*)d_in[1];
    const float* W          = (const float*)d_in[2];
    float*       out        = (float*)d_out;

    int E = in_sizes[0] / 2;
    int N = in_sizes[1] / D;
    int nb = (N + SCAN_B - 1) / SCAN_B;   // 98 for N=100000 (<=128, <=148 SMs)

    k_zero<<<(N + 255) / 256, 256>>>(N);
    k_degree<<<2048, 256>>>(edge_index, E);
    k_scan<<<nb, SCAN_B>>>(N);
    k_fill<<<2048, 256>>>(edge_index, E);
    k_gemm<<<GEMM_GRID, 256>>>(x, W, N);
    k_gather<<<2048, 256>>>(out, N);
}

// round 9
// speedup vs baseline: 1.1080x; 1.1080x over previous
#include <cuda_runtime.h>
#include <cuda_fp16.h>
#include <cuda_bf16.h>

#define NMAX 100000
#define EMAX 1600000
#define D 64
#define SCAN_B 1024
#define SCAN_MAXBLK 128

// __device__ scratch (no allocations allowed)
__device__ int    g_deg[NMAX];
__device__ int    g_rowstart[NMAX];
__device__ float  g_dinv[NMAX];
__device__ __half g_xh[(size_t)NMAX * D];   // fp16, pre-scaled by dinv[node]
__device__ int    g_ecol[EMAX];
__device__ int    g_rank[EMAX];             // within-row rank of each edge

// decoupled-lookback state: ONE 64-bit word per block = (flag<<32) | value.
// flag: 0 = invalid, 1 = aggregate, 2 = inclusive prefix. 8B accesses are
// single-copy atomic -> consistent (flag,value) snapshot in one load.
__device__ volatile unsigned long long g_scan_pair[SCAN_MAXBLK];

// packed fp32x2 FMA (Blackwell)
__device__ __forceinline__ void fma_f32x2(unsigned long long& d,
                                          unsigned long long a,
                                          unsigned long long b,
                                          unsigned long long c) {
    asm("fma.rn.f32x2 %0, %1, %2, %3;" : "=l"(d) : "l"(a), "l"(b), "l"(c));
}
__device__ __forceinline__ unsigned smem_u32(const void* p) {
    return (unsigned)__cvta_generic_to_shared(p);
}
__device__ __forceinline__ void cp_async16(unsigned s, const void* g) {
    asm volatile("cp.async.cg.shared.global [%0], [%1], 16;" :: "r"(s), "l"(g));
}
__device__ __forceinline__ void cp_commit() { asm volatile("cp.async.commit_group;"); }
template <int N> __device__ __forceinline__ void cp_wait() {
    asm volatile("cp.async.wait_group %0;" :: "n"(N));
}

// ---------------------------------------------------------------------------
// zero degree + scan state
// ---------------------------------------------------------------------------
__global__ void k_zero(int N) {
    int i = blockIdx.x * blockDim.x + threadIdx.x;
    if (i < N) g_deg[i] = 0;
    if (i < SCAN_MAXBLK) g_scan_pair[i] = 0ULL;
}

// ---------------------------------------------------------------------------
// degree histogram + per-edge within-row rank (free from the atomic return)
// ---------------------------------------------------------------------------
__global__ void k_degree(const int* __restrict__ rowp, int E) {
    int i = blockIdx.x * blockDim.x + threadIdx.x;
    int stride = gridDim.x * blockDim.x;
    for (int e = i; e < E; e += stride) {
        int r = __ldg(rowp + e);
        g_rank[e] = atomicAdd(&g_deg[r], 1);
    }
}

// ---------------------------------------------------------------------------
// single-pass scan, WARP-PARALLEL decoupled lookback:
// g_deg -> exclusive g_rowstart + dinv.  98 blocks co-resident on 148 SMs.
// ---------------------------------------------------------------------------
__global__ void __launch_bounds__(SCAN_B) k_scan(int N) {
    __shared__ int wsum[32];
    __shared__ int s_base;

    int bid = blockIdx.x;
    int i = bid * SCAN_B + threadIdx.x;
    int lane = threadIdx.x & 31;
    int wid = threadIdx.x >> 5;

    int v = (i < N) ? g_deg[i] : 0;

    // warp inclusive scan
    int s = v;
#pragma unroll
    for (int off = 1; off < 32; off <<= 1) {
        int t = __shfl_up_sync(0xffffffffu, s, off);
        if (lane >= off) s += t;
    }
    if (lane == 31) wsum[wid] = s;
    __syncthreads();
    if (wid == 0) {
        int ws = wsum[lane];
#pragma unroll
        for (int off = 1; off < 32; off <<= 1) {
            int t = __shfl_up_sync(0xffffffffu, ws, off);
            if (lane >= off) ws += t;
        }
        wsum[lane] = ws;
    }
    __syncthreads();
    int incl = s + ((wid > 0) ? wsum[wid - 1] : 0);
    int block_total = wsum[31];

    // warp 0: publish + windowed lookback (32 predecessors per round)
    if (wid == 0) {
        if (bid == 0) {
            if (lane == 0) {
                g_scan_pair[0] = (2ULL << 32) | (unsigned)block_total;
                s_base = 0;
            }
        } else {
            if (lane == 0)
                g_scan_pair[bid] = (1ULL << 32) | (unsigned)block_total;
            __syncwarp();

            int base = 0;
            int wstart = bid - 1;
            while (true) {
                int j = wstart - lane;            // lane 0 = nearest predecessor
                unsigned flag = 0, val = 0;
                if (j >= 0) {
                    unsigned long long p;
                    do { p = g_scan_pair[j]; } while ((p >> 32) == 0ULL);
                    flag = (unsigned)(p >> 32);
                    val = (unsigned)p;
                }
                unsigned b2 = __ballot_sync(0xffffffffu, flag == 2u);
                if (b2) {
                    int lp = __ffs(b2) - 1;       // nearest block with a prefix
                    unsigned contrib = (lane <= lp) ? val : 0u;
                    base += (int)__reduce_add_sync(0xffffffffu, contrib);
                    break;
                } else {
                    base += (int)__reduce_add_sync(0xffffffffu, val);
                    wstart -= 32;
                }
            }
            if (lane == 0) {
                g_scan_pair[bid] = (2ULL << 32) | (unsigned)(base + block_total);
                s_base = base;
            }
        }
    }
    __syncthreads();

    if (i < N) {
        g_rowstart[i] = s_base + incl - v;
        g_dinv[i] = (v > 0) ? rsqrtf((float)v) : 0.0f;
    }
}

// ---------------------------------------------------------------------------
// CSR fill: NO atomics. p = rowstart[row] + precomputed rank. Stores are
// fire-and-forget; loads have full MLP.
// ---------------------------------------------------------------------------
__global__ void k_fill(const int* __restrict__ ei, int E) {
    int i = blockIdx.x * blockDim.x + threadIdx.x;
    int stride = gridDim.x * blockDim.x;
    const int* rowp = ei;
    const int* colp = ei + E;
    for (int e = i; e < E; e += stride) {
        int r = __ldg(rowp + e);
        int c = __ldg(colp + e);
        int p = g_rowstart[r] + g_rank[e];
        g_ecol[p] = c;
    }
}

// ---------------------------------------------------------------------------
// GEMM: xh_h[r] = fp16( dinv[r] * (x[r] @ W^T) ).  Persistent, W-stationary
// (f32x2), cp.async double-buffered tiles, 32 rows/tile, 8 rows/thread.
// ---------------------------------------------------------------------------
#define GEMM_ROWS 32
#define RPT 8
#define GEMM_GRID 296

__global__ void __launch_bounds__(256) k_gemm(const float* __restrict__ x,
                                              const float* __restrict__ W, int N) {
    __shared__ float  Ws[D * (D + 1)];
    __shared__ float2 xs[2][GEMM_ROWS][D / 2];

    int tid = threadIdx.x;
    int tx = tid & 63;
    int ty = tid >> 6;

    for (int i = tid; i < D * D; i += 256)
        Ws[(i >> 6) * (D + 1) + (i & 63)] = W[i];
    __syncthreads();

    unsigned long long w2[D / 2];
#pragma unroll
    for (int k2 = 0; k2 < D / 2; k2++) {
        float2 p = make_float2(Ws[tx * (D + 1) + 2 * k2], Ws[tx * (D + 1) + 2 * k2 + 1]);
        w2[k2] = *reinterpret_cast<unsigned long long*>(&p);
    }
    __syncthreads();

    int ntiles = (N + GEMM_ROWS - 1) / GEMM_ROWS;

    auto issue = [&](int t, int buf) {
        const float4* src = reinterpret_cast<const float4*>(x + (size_t)t * GEMM_ROWS * D);
        int limit = (N - t * GEMM_ROWS) * (D / 4);
        unsigned sbase = smem_u32(&xs[buf][0][0]);
#pragma unroll
        for (int rnd = 0; rnd < 2; rnd++) {
            int v = tid + rnd * 256;
            if (v < 512 && v < limit) cp_async16(sbase + v * 16, src + v);
        }
        cp_commit();
    };

    int t = blockIdx.x;
    if (t < ntiles) issue(t, 0);
    int buf = 0;

    for (; t < ntiles; t += GEMM_GRID) {
        int tn = t + GEMM_GRID;
        bool have_next = (tn < ntiles);
        if (have_next) issue(tn, buf ^ 1);

        if (have_next) cp_wait<1>(); else cp_wait<0>();
        __syncthreads();

        int r0 = ty * RPT;
        unsigned long long acc[RPT];
#pragma unroll
        for (int i = 0; i < RPT; i++) acc[i] = 0ULL;

#pragma unroll
        for (int k2 = 0; k2 < D / 2; k2++) {
            unsigned long long wreg = w2[k2];
#pragma unroll
            for (int i = 0; i < RPT; i++) {
                float2 xv = xs[buf][r0 + i][k2];
                unsigned long long xp = *reinterpret_cast<unsigned long long*>(&xv);
                fma_f32x2(acc[i], xp, wreg, acc[i]);
            }
        }

        int rb = t * GEMM_ROWS;
#pragma unroll
        for (int i = 0; i < RPT; i++) {
            int r = rb + r0 + i;
            if (r < N) {
                float2 p = *reinterpret_cast<float2*>(&acc[i]);
                float dr = g_dinv[r];
                g_xh[(size_t)r * D + tx] = __float2half_rn(dr * (p.x + p.y));
            }
        }
        __syncthreads();
        buf ^= 1;
    }
}

// ---------------------------------------------------------------------------
// Gather: warp per row, fp16 pre-scaled rows, pure half2->float2 accumulate.
// out[r] = dinv[r] * sum_j xh_h[c_j]
// ---------------------------------------------------------------------------
__global__ void k_gather(float* __restrict__ out, int N) {
    int gtid = blockIdx.x * blockDim.x + threadIdx.x;
    int warp = gtid >> 5;
    int lane = threadIdx.x & 31;
    int nwarps = (gridDim.x * blockDim.x) >> 5;

    const __half2* xh2 = reinterpret_cast<const __half2*>(g_xh);

    for (int r = warp; r < N; r += nwarps) {
        int s = g_rowstart[r];
        int e = s + g_deg[r];

        float ax = 0.f, ay = 0.f, bx = 0.f, by = 0.f;
        float cx = 0.f, cy = 0.f, dx = 0.f, dy = 0.f;

        int j = s;
        for (; j + 3 < e; j += 4) {
            int c0 = g_ecol[j];
            int c1 = g_ecol[j + 1];
            int c2 = g_ecol[j + 2];
            int c3 = g_ecol[j + 3];
            float2 f0 = __half22float2(xh2[(size_t)c0 * 32 + lane]);
            float2 f1 = __half22float2(xh2[(size_t)c1 * 32 + lane]);
            float2 f2 = __half22float2(xh2[(size_t)c2 * 32 + lane]);
            float2 f3 = __half22float2(xh2[(size_t)c3 * 32 + lane]);
            ax += f0.x; ay += f0.y;
            bx += f1.x; by += f1.y;
            cx += f2.x; cy += f2.y;
            dx += f3.x; dy += f3.y;
        }
        for (; j < e; j++) {
            int c = g_ecol[j];
            float2 f = __half22float2(xh2[(size_t)c * 32 + lane]);
            ax += f.x; ay += f.y;
        }

        float dr = g_dinv[r];
        float2 res = make_float2(dr * (ax + bx + cx + dx),
                                 dr * (ay + by + cy + dy));
        reinterpret_cast<float2*>(out)[(size_t)r * 32 + lane] = res;
    }
}

// ---------------------------------------------------------------------------
// launch
// ---------------------------------------------------------------------------
extern "C" void kernel_launch(void* const* d_in, const int* in_sizes, int n_in,
                              void* d_out, int out_size) {
    const int*   edge_index = (const int*)d_in[0];
    const float* x          = (const float*)d_in[1];
    const float* W          = (const float*)d_in[2];
    float*       out        = (float*)d_out;

    int E = in_sizes[0] / 2;
    int N = in_sizes[1] / D;
    int nb = (N + SCAN_B - 1) / SCAN_B;   // 98 for N=100000 (<=128, <=148 SMs)

    k_zero<<<(N + 255) / 256, 256>>>(N);
    k_degree<<<2048, 256>>>(edge_index, E);
    k_scan<<<nb, SCAN_B>>>(N);
    k_fill<<<2048, 256>>>(edge_index, E);
    k_gemm<<<GEMM_GRID, 256>>>(x, W, N);
    k_gather<<<2048, 256>>>(out, N);
}